// round 15
// baseline (speedup 1.0000x reference)
#include <cuda_runtime.h>
#include <math.h>

#define DEC_DIM 1024
#define ENC_DIM 1024
#define BATCH   32
#define SRCLEN  2048

// e_dec[b] = dec_hidden[b].w_dec + bias, computed by block 0 of score_kernel
// (overlapped with the main HBM stream), consumed by softmax_kernel.
__device__ float g_edec[BATCH];

// ---------------------------------------------------------------------------
// Kernel 1: out[b*SRCLEN + s] = enc[s,b,:] . w_enc      (raw dot)
// One warp per (s,b) row; r = s*32 + b matches enc memory order so
// consecutive warps stream consecutive 4KB rows. HBM-bound: 268MB read once.
// Block 0 additionally computes g_edec[0..31] (hidden under the stream).
// ---------------------------------------------------------------------------
__global__ void __launch_bounds__(256)
score_kernel(const float* __restrict__ enc,        // [SRCLEN][BATCH][ENC_DIM]
             const float* __restrict__ dec_hidden, // [BATCH][DEC_DIM]
             const float* __restrict__ W,          // w_enc = W + DEC_DIM
             const float* __restrict__ bias,
             float* __restrict__ out) {
    __shared__ float4 s_w[ENC_DIM / 4];
    const float4* we = reinterpret_cast<const float4*>(W + DEC_DIM);
    for (int i = threadIdx.x; i < ENC_DIM / 4; i += blockDim.x) s_w[i] = we[i];
    __syncthreads();

    const int warp = threadIdx.x >> 5;
    const int lane = threadIdx.x & 31;
    const int r = blockIdx.x * 8 + warp;          // r = s*32 + b, < 65536
    const float4* row = reinterpret_cast<const float4*>(enc) + (long long)r * (ENC_DIM / 4);

    float sum = 0.f;
#pragma unroll
    for (int i = 0; i < 8; i++) {
        float4 a = __ldcs(row + lane + 32 * i);   // streaming: no reuse, 268MB > L2
        float4 w = s_w[lane + 32 * i];
        sum += a.x * w.x + a.y * w.y + a.z * w.z + a.w * w.w;
    }
#pragma unroll
    for (int o = 16; o; o >>= 1) sum += __shfl_xor_sync(0xffffffffu, sum, o);

    if (lane == 0) {
        const int b = r & 31;
        const int s = r >> 5;
        out[b * SRCLEN + s] = sum;
    }

    // Block 0: compute e_dec for all 32 batch rows (4 per warp), overlapped
    // with the global stream. Visible to softmax_kernel at launch boundary.
    if (blockIdx.x == 0) {
        const float4* wd = reinterpret_cast<const float4*>(W);
#pragma unroll
        for (int j = 0; j < 4; j++) {
            const int b = warp + 8 * j;
            const float4* dh = reinterpret_cast<const float4*>(dec_hidden + b * DEC_DIM);
            float es = 0.f;
#pragma unroll
            for (int i = 0; i < 8; i++) {
                float4 a = dh[lane + 32 * i];
                float4 w = wd[lane + 32 * i];
                es += a.x * w.x + a.y * w.y + a.z * w.z + a.w * w.w;
            }
#pragma unroll
            for (int o = 16; o; o >>= 1) es += __shfl_xor_sync(0xffffffffu, es, o);
            if (lane == 0) g_edec[b] = es + bias[0];
        }
    }
}

// ---------------------------------------------------------------------------
// Kernel 2: per batch row b: v[s] = tanh(out[b,s] + e_dec[b]);
//           out[b,:] = exp(v) / sum(exp(v)).
// NO max pass: tanh output is in [-1,1] so exp cannot overflow — identical
// result to max-subtracted softmax. 1024 threads/block, 2 elems/thread.
// ---------------------------------------------------------------------------
__global__ void __launch_bounds__(1024)
softmax_kernel(float* __restrict__ out) {
    const int b = blockIdx.x;
    const int t = threadIdx.x;
    const int lane = t & 31;
    const int warp = t >> 5;
    float* row = out + b * SRCLEN;

    __shared__ float red[32];
    __shared__ float s_inv;

    const float edec = g_edec[b];

    // load + tanh + exp for both elements (independent chains)
    float r0 = __ldcg(row + t);
    float r1 = __ldcg(row + t + 1024);
    float p0 = __expf(tanhf(r0 + edec));
    float p1 = __expf(tanhf(r1 + edec));

    float s = p0 + p1;
#pragma unroll
    for (int o = 16; o; o >>= 1) s += __shfl_xor_sync(0xffffffffu, s, o);
    if (lane == 0) red[warp] = s;
    __syncthreads();
    if (warp == 0) {
        float v = red[lane];
#pragma unroll
        for (int o = 16; o; o >>= 1) v += __shfl_xor_sync(0xffffffffu, v, o);
        if (lane == 0) s_inv = 1.0f / v;
    }
    __syncthreads();
    const float inv = s_inv;

    row[t]        = p0 * inv;
    row[t + 1024] = p1 * inv;
}

// ---------------------------------------------------------------------------
extern "C" void kernel_launch(void* const* d_in, const int* in_sizes, int n_in,
                              void* d_out, int out_size) {
    const float* dec_hidden = (const float*)d_in[0];
    const float* enc        = (const float*)d_in[1];
    const float* W          = (const float*)d_in[2];
    const float* bias       = (const float*)d_in[3];
    float* out = (float*)d_out;

    score_kernel<<<(SRCLEN * BATCH) / 8, 256>>>(enc, dec_hidden, W, bias, out);
    softmax_kernel<<<BATCH, 1024>>>(out);
}